// round 9
// baseline (speedup 1.0000x reference)
#include <cuda_runtime.h>
#include <math.h>

// Problem constants
#define BB 4096
#define KK 64
#define FF 128
#define TE 32
#define DD 160
#define NT 10000
#define INV_SQRT_D 0.07905694150420949f   // 1/sqrt(160)

// ---------------- scratch (__device__ globals; no allocation allowed) ----------
__device__ float g_tbl[NT * TE];     // cos(t*w+b) table, 1.28MB
__device__ float g_M[DD * DD];       // Wk^T Wq / sqrt(D)
__device__ float g_P[DD * DD];       // out_w @ Wv
__device__ float g_m0[DD];           // Wk^T bq / sqrt(D)
__device__ float g_w0[DD];           // Wq^T bk / sqrt(D)
__device__ float g_p0[DD];           // out_w @ bv + out_b
__device__ float g_b00[1];           // bq.bk / sqrt(D)
__device__ float g_U[BB * DD];       // per-target transformed query
__device__ float g_S0[BB];           // per-target score bias
__device__ float g_Acc[BB * DD];     // attn-weighted kv accumulation

// ---------------- kernel 0a: fold weight matrices ------------------------------
// grid 2*DD+1 blocks x DD threads
__global__ void prep_kernel(const float* __restrict__ ipw,
                            const float* __restrict__ ipb,
                            const float* __restrict__ outw,
                            const float* __restrict__ outb) {
    int t = threadIdx.x;
    int bidx = blockIdx.x;
    if (bidx < DD) {
        // M[f,g] = sum_d Wk[d,f] * Wq[d,g] / sqrt(D)   (f = bidx, g = t)
        int f = bidx;
        float acc = 0.f;
        for (int d = 0; d < DD; ++d)
            acc = fmaf(ipw[(DD + d) * DD + f], ipw[d * DD + t], acc);
        g_M[f * DD + t] = acc * INV_SQRT_D;
    } else if (bidx < 2 * DD) {
        // P[e,g] = sum_d out_w[e,d] * Wv[d,g]   (e = bidx-DD, g = t)
        int e = bidx - DD;
        float acc = 0.f;
        for (int d = 0; d < DD; ++d)
            acc = fmaf(outw[e * DD + d], ipw[(2 * DD + d) * DD + t], acc);
        g_P[e * DD + t] = acc;
    } else {
        float m0 = 0.f, w0 = 0.f, p0 = 0.f;
        for (int d = 0; d < DD; ++d) {
            m0 = fmaf(ipw[(DD + d) * DD + t], ipb[d], m0);        // Wk[d,t]*bq[d]
            w0 = fmaf(ipw[d * DD + t], ipb[DD + d], w0);          // Wq[d,t]*bk[d]
            p0 = fmaf(outw[t * DD + d], ipb[2 * DD + d], p0);     // out_w[t,d]*bv[d]
        }
        g_m0[t] = m0 * INV_SQRT_D;
        g_w0[t] = w0 * INV_SQRT_D;
        g_p0[t] = p0 + outb[t];
        if (t == 0) {
            float b00 = 0.f;
            for (int d = 0; d < DD; ++d) b00 = fmaf(ipb[d], ipb[DD + d], b00);
            g_b00[0] = b00 * INV_SQRT_D;
        }
    }
}

// ---------------- kernel 0b: cos table -----------------------------------------
__global__ void tbl_kernel(const float* __restrict__ tw, const float* __restrict__ tb) {
    int idx = blockIdx.x * blockDim.x + threadIdx.x;
    if (idx >= NT * TE) return;
    int t = idx >> 5;
    int j = idx & 31;
    // match reference: f32 multiply then f32 add (no fma contraction), accurate cos
    float arg = __fadd_rn(__fmul_rn((float)t, tw[j]), tb[j]);
    g_tbl[idx] = (float)cos((double)arg);
}

// ---------------- kernel 1: U = M @ q_in + m0, S0 -------------------------------
// grid 128 blocks x 256 thr, each block handles 32 targets, M cached in smem
__global__ void phase1_kernel(const float* __restrict__ x,
                              const int* __restrict__ tgt_ids,
                              const int* __restrict__ tgt_times) {
    extern __shared__ float sh[];
    float* sM   = sh;                   // DD x 161 (padded)
    float* qin  = sM + DD * 161;        // DD
    float* m0s  = qin + DD;             // DD
    float* w0s  = m0s + DD;             // DD
    float* sred = w0s + DD;             // DD
    int t = threadIdx.x;

    for (int i = t; i < DD * DD; i += blockDim.x)
        sM[(i / DD) * 161 + (i % DD)] = g_M[i];
    if (t < DD) { m0s[t] = g_m0[t]; w0s[t] = g_w0[t]; }
    __syncthreads();

    int b0 = blockIdx.x * 32;
    for (int bb = 0; bb < 32; ++bb) {
        int b = b0 + bb;
        int tg = tgt_ids[b];
        int tt = tgt_times[b];
        if (t < FF)       qin[t] = x[tg * FF + t];
        else if (t < DD)  qin[t] = g_tbl[tt * TE + (t - FF)];
        __syncthreads();
        if (t < DD) {
            float acc = m0s[t];
            const float* Mr = &sM[t * 161];
#pragma unroll 8
            for (int g = 0; g < DD; ++g) acc = fmaf(Mr[g], qin[g], acc);
            g_U[b * DD + t] = acc;
            sred[t] = qin[t] * w0s[t];
        }
        __syncthreads();
        if (t < 32) {
            float v = sred[t] + sred[t + 32] + sred[t + 64] + sred[t + 96] + sred[t + 128];
            for (int o = 16; o; o >>= 1) v += __shfl_xor_sync(0xffffffffu, v, o);
            if (t == 0) g_S0[b] = v + g_b00[0];
        }
        __syncthreads();
    }
}

// ---------------- kernel 2: scores, softmax, gumbel/mask, accumulation ----------
// 1 block per target b, 512 threads (16 warps), each warp owns 4 neighbors.
__global__ void __launch_bounds__(512)
phase2_kernel(const float* __restrict__ x,
              const int* __restrict__ nbr_ids,
              const int* __restrict__ etime,
              const float* __restrict__ gum,
              float* __restrict__ out_mask) {
    __shared__ float ssc[KK];
    __shared__ float saw[KK];
    __shared__ float4 part[16][41];   // 16 warps x 40 float4 (padded to 41)

    int b = blockIdx.x;
    int t = threadIdx.x;
    int w = t >> 5;
    int lane = t & 31;
    int kb = w * 4;

    const float4* xv = (const float4*)x;
    const float4* tv = (const float4*)g_tbl;
    const float4* uv = (const float4*)g_U;

    float4 u4 = uv[b * 40 + lane];                       // elements 4*lane..4*lane+3
    float4 ut4 = make_float4(0.f, 0.f, 0.f, 0.f);
    if (lane < 8) ut4 = uv[b * 40 + 32 + lane];          // TE part
    float s0 = g_S0[b];

    int nid[4], et[4];
    float4 xr[4], tr[4];
#pragma unroll
    for (int i = 0; i < 4; ++i) {
        nid[i] = nbr_ids[b * KK + kb + i];
        et[i]  = etime[b * KK + kb + i];
    }
#pragma unroll
    for (int i = 0; i < 4; ++i) xr[i] = xv[nid[i] * 32 + lane];   // coalesced 512B row
#pragma unroll
    for (int i = 0; i < 4; ++i)
        tr[i] = (lane < 8) ? tv[et[i] * 8 + lane] : make_float4(0.f, 0.f, 0.f, 0.f);

#pragma unroll
    for (int i = 0; i < 4; ++i) {
        float p = u4.x * xr[i].x + u4.y * xr[i].y + u4.z * xr[i].z + u4.w * xr[i].w
                + ut4.x * tr[i].x + ut4.y * tr[i].y + ut4.z * tr[i].z + ut4.w * tr[i].w;
        for (int o = 16; o; o >>= 1) p += __shfl_xor_sync(0xffffffffu, p, o);
        if (lane == 0) ssc[kb + i] = p + s0;
    }
    __syncthreads();

    if (w == 0) {
        // softmax over 64 scores: lane handles l and l+32
        float a0 = ssc[lane], a1 = ssc[lane + 32];
        float m = fmaxf(a0, a1);
        for (int o = 16; o; o >>= 1) m = fmaxf(m, __shfl_xor_sync(0xffffffffu, m, o));
        float e0 = expf(a0 - m), e1 = expf(a1 - m);
        float s = e0 + e1;
        for (int o = 16; o; o >>= 1) s += __shfl_xor_sync(0xffffffffu, s, o);
        float aw0 = e0 / s, aw1 = e1 / s;
        saw[lane] = aw0;
        saw[lane + 32] = aw1;
        // gumbel softmax + threshold mask (TAU = 1)
        float gu0 = gum[b * KK + lane], gu1 = gum[b * KK + lane + 32];
        float g0 = -logf(-logf(gu0 + 1e-10f) + 1e-10f);
        float g1 = -logf(-logf(gu1 + 1e-10f) + 1e-10f);
        float z0 = aw0 + g0, z1 = aw1 + g1;
        float zm = fmaxf(z0, z1);
        for (int o = 16; o; o >>= 1) zm = fmaxf(zm, __shfl_xor_sync(0xffffffffu, zm, o));
        float ez0 = expf(z0 - zm), ez1 = expf(z1 - zm);
        float zs = ez0 + ez1;
        for (int o = 16; o; o >>= 1) zs += __shfl_xor_sync(0xffffffffu, zs, o);
        out_mask[b * KK + lane]      = (ez0 / zs > 0.2f) ? 1.0f : 0.0f;
        out_mask[b * KK + lane + 32] = (ez1 / zs > 0.2f) ? 1.0f : 0.0f;
    }
    __syncthreads();

    // accumulate attn_w-weighted kv rows (kv still live in registers)
    float4 ax = make_float4(0.f, 0.f, 0.f, 0.f);
    float4 at = make_float4(0.f, 0.f, 0.f, 0.f);
#pragma unroll
    for (int i = 0; i < 4; ++i) {
        float aw = saw[kb + i];
        ax.x = fmaf(aw, xr[i].x, ax.x);
        ax.y = fmaf(aw, xr[i].y, ax.y);
        ax.z = fmaf(aw, xr[i].z, ax.z);
        ax.w = fmaf(aw, xr[i].w, ax.w);
        at.x = fmaf(aw, tr[i].x, at.x);
        at.y = fmaf(aw, tr[i].y, at.y);
        at.z = fmaf(aw, tr[i].z, at.z);
        at.w = fmaf(aw, tr[i].w, at.w);
    }
    part[w][lane] = ax;
    if (lane < 8) part[w][32 + lane] = at;
    __syncthreads();

    if (t < DD) {
        const float* pf = (const float*)part;   // row stride 41*4 = 164 floats
        float a = 0.f;
#pragma unroll
        for (int ww = 0; ww < 16; ++ww) a += pf[ww * 164 + t];
        g_Acc[b * DD + t] = a;
    }
}

// ---------------- kernel 3: attn_out = P @ acc + p0, mlp + leaky ----------------
// grid 128 blocks x 256 thr, each handles 32 targets, P cached in smem
__global__ void phase3_kernel(const float* __restrict__ ew,
                              const float* __restrict__ mlpw,
                              const float* __restrict__ mlpb,
                              float* __restrict__ out1,
                              float* __restrict__ out2) {
    extern __shared__ float sh[];
    float* sP   = sh;                    // DD x 161
    float* sacc = sP + DD * 161;         // DD
    float* sp0  = sacc + DD;             // DD
    float* smlp = sp0 + DD;              // 161
    float* sred = smlp + 161;            // DD
    float* sdot = sred + DD;             // 2 (dot, mlp_b)
    int t = threadIdx.x;

    for (int i = t; i < DD * DD; i += blockDim.x)
        sP[(i / DD) * 161 + (i % DD)] = g_P[i];
    if (t < DD) sp0[t] = g_p0[t];
    if (t < 161) smlp[t] = mlpw[t];
    if (t == 0) sdot[1] = mlpb[0];
    __syncthreads();

    int b0 = blockIdx.x * 32;
    for (int bb = 0; bb < 32; ++bb) {
        int b = b0 + bb;
        if (t < DD) sacc[t] = g_Acc[b * DD + t];
        __syncthreads();
        if (t < DD) {
            float acc = sp0[t];
            const float* Pr = &sP[t * 161];
#pragma unroll 8
            for (int f = 0; f < DD; ++f) acc = fmaf(Pr[f], sacc[f], acc);
            out1[b * DD + t] = acc;
            sred[t] = acc * smlp[t];
        }
        __syncthreads();
        if (t < 32) {
            float v = sred[t] + sred[t + 32] + sred[t + 64] + sred[t + 96] + sred[t + 128];
            for (int o = 16; o; o >>= 1) v += __shfl_xor_sync(0xffffffffu, v, o);
            if (t == 0) sdot[0] = v;
        }
        __syncthreads();
        if (t < KK) {
            float e = ew[b * KK + t];
            float v = sdot[0] + fmaf(e, smlp[160], sdot[1]);
            out2[b * KK + t] = (v >= 0.f) ? v : 0.01f * v;
        }
        __syncthreads();
    }
}

// ---------------- launch --------------------------------------------------------
extern "C" void kernel_launch(void* const* d_in, const int* in_sizes, int n_in,
                              void* d_out, int out_size) {
    const float* x    = (const float*)d_in[0];
    const int*   tgt  = (const int*)  d_in[1];
    const int*   tt   = (const int*)  d_in[2];
    const int*   nbr  = (const int*)  d_in[3];
    const int*   et   = (const int*)  d_in[4];
    const float* ew   = (const float*)d_in[5];
    const float* gu   = (const float*)d_in[6];
    const float* tew  = (const float*)d_in[7];
    const float* teb  = (const float*)d_in[8];
    const float* ipw  = (const float*)d_in[9];
    const float* ipb  = (const float*)d_in[10];
    const float* outw = (const float*)d_in[11];
    const float* outb = (const float*)d_in[12];
    const float* mlpw = (const float*)d_in[13];
    const float* mlpb = (const float*)d_in[14];

    float* o1 = (float*)d_out;           // attn_output  [B, D]
    float* o2 = o1 + BB * DD;            // new_edge_weight [B, K]
    float* o3 = o2 + BB * KK;            // candidate_mask  [B, K]

    size_t sm1 = (size_t)(DD * 161 + 4 * DD) * sizeof(float);
    size_t sm3 = (size_t)(DD * 161 + DD + DD + 161 + DD + 2) * sizeof(float);
    cudaFuncSetAttribute(phase1_kernel, cudaFuncAttributeMaxDynamicSharedMemorySize, 110 * 1024);
    cudaFuncSetAttribute(phase3_kernel, cudaFuncAttributeMaxDynamicSharedMemorySize, 110 * 1024);

    prep_kernel<<<2 * DD + 1, DD>>>(ipw, ipb, outw, outb);
    tbl_kernel<<<(NT * TE + 255) / 256, 256>>>(tew, teb);
    phase1_kernel<<<128, 256, sm1>>>(x, tgt, tt);
    phase2_kernel<<<BB, 512>>>(x, nbr, et, gu, o3);
    phase3_kernel<<<128, 256, sm3>>>(ew, mlpw, mlpb, o1, o2);
}

// round 10
// speedup vs baseline: 1.9743x; 1.9743x over previous
#include <cuda_runtime.h>
#include <math.h>

// Problem constants
#define BB 4096
#define KK 64
#define FF 128
#define TE 32
#define DD 160
#define NT 10000
#define INV_SQRT_D 0.07905694150420949f   // 1/sqrt(160)

// ---------------- scratch (__device__ globals; no allocation allowed) ----------
__device__ __align__(16) float g_tbl[NT * TE];   // cos(t*w+b) table, 1.28MB
__device__ __align__(16) float g_Mt[DD * DD];    // Mt[g][o] = (Wk^T Wq / sqrt(D))[o][g]
__device__ __align__(16) float g_Pt[DD * DD];    // Pt[g][e] = (out_w @ Wv)[e][g]
__device__ float g_m0[DD];                       // Wk^T bq / sqrt(D)
__device__ float g_w0[DD];                       // Wq^T bk / sqrt(D)
__device__ float g_p0[DD];                       // out_w @ bv + out_b
__device__ float g_b00[1];                       // bq.bk / sqrt(D)
__device__ __align__(16) float g_Qin[BB * DD];   // gathered target q_in rows
__device__ __align__(16) float g_U[BB * DD];     // per-target transformed query
__device__ float g_S0[BB];                       // per-target score bias
__device__ __align__(16) float g_Acc[BB * DD];   // attn-weighted kv accumulation

// ---------------- kernel 0a: fold weight matrices (transposed outputs) ----------
// grid 2*DD+1 blocks x DD threads
__global__ void prep_kernel(const float* __restrict__ ipw,
                            const float* __restrict__ ipb,
                            const float* __restrict__ outw,
                            const float* __restrict__ outb) {
    int t = threadIdx.x;
    int bidx = blockIdx.x;
    if (bidx < DD) {
        // M[f,g] = sum_d Wk[d,f] * Wq[d,g] / sqrt(D)   (f = bidx, g = t)
        int f = bidx;
        float acc = 0.f;
        for (int d = 0; d < DD; ++d)
            acc = fmaf(ipw[(DD + d) * DD + f], ipw[d * DD + t], acc);
        // store transposed for GEMM: Mt[g][o] = M[o][g], o=f, g=t
        g_Mt[t * DD + f] = acc * INV_SQRT_D;
    } else if (bidx < 2 * DD) {
        // P[e,g] = sum_d out_w[e,d] * Wv[d,g]   (e = bidx-DD, g = t)
        int e = bidx - DD;
        float acc = 0.f;
        for (int d = 0; d < DD; ++d)
            acc = fmaf(outw[e * DD + d], ipw[(2 * DD + d) * DD + t], acc);
        g_Pt[t * DD + e] = acc;
    } else {
        float m0 = 0.f, w0 = 0.f, p0 = 0.f;
        for (int d = 0; d < DD; ++d) {
            m0 = fmaf(ipw[(DD + d) * DD + t], ipb[d], m0);        // Wk[d,t]*bq[d]
            w0 = fmaf(ipw[d * DD + t], ipb[DD + d], w0);          // Wq[d,t]*bk[d]
            p0 = fmaf(outw[t * DD + d], ipb[2 * DD + d], p0);     // out_w[t,d]*bv[d]
        }
        g_m0[t] = m0 * INV_SQRT_D;
        g_w0[t] = w0 * INV_SQRT_D;
        g_p0[t] = p0 + outb[t];
        if (t == 0) {
            float b00 = 0.f;
            for (int d = 0; d < DD; ++d) b00 = fmaf(ipb[d], ipb[DD + d], b00);
            g_b00[0] = b00 * INV_SQRT_D;
        }
    }
}

// ---------------- kernel 0b: cos table (double range-reduction + cosf) ----------
__global__ void tbl_kernel(const float* __restrict__ tw, const float* __restrict__ tb) {
    int idx = blockIdx.x * blockDim.x + threadIdx.x;
    if (idx >= NT * TE) return;
    int t = idx >> 5;
    int j = idx & 31;
    // match reference: f32 multiply then f32 add (no fma contraction)
    float arg = __fadd_rn(__fmul_rn((float)t, tw[j]), tb[j]);
    // k exact in fp32 (|k| < 2^13); subtract k*2pi in double (err ~1e-12)
    float kf = rintf(arg * 0.15915494309189535f);
    double r = fma(-(double)kf, 6.283185307179586, (double)arg);
    g_tbl[idx] = cosf((float)r);
}

// ---------------- kernel 1a: gather q_in rows + S0 ------------------------------
// grid 128 x 1024; warp per target
__global__ void __launch_bounds__(1024)
gather_kernel(const float* __restrict__ x,
              const int* __restrict__ tgt_ids,
              const int* __restrict__ tgt_times) {
    __shared__ float w0s[DD + 1];
    int t = threadIdx.x, w = t >> 5, lane = t & 31;
    if (t < DD) w0s[t] = g_w0[t];
    if (t == DD) w0s[DD] = g_b00[0];
    __syncthreads();

    int b = blockIdx.x * 32 + w;
    int tg = tgt_ids[b];
    int tt = tgt_times[b];
    float s = 0.f;
#pragma unroll
    for (int m = 0; m < 5; ++m) {
        int c = lane + 32 * m;
        float v = (c < FF) ? x[tg * FF + c] : g_tbl[tt * TE + (c - FF)];
        g_Qin[b * DD + c] = v;
        s = fmaf(v, w0s[c], s);
    }
#pragma unroll
    for (int o = 16; o; o >>= 1) s += __shfl_xor_sync(0xffffffffu, s, o);
    if (lane == 0) g_S0[b] = s + w0s[DD];
}

// ---------------- shared GEMM: C[b][o] = bias[o] + sum_g A[b][g]*Bt[g][o] -------
// A:[4096][160], Bt:[160][160]. 128 blocks x 256 thr, 32b x 160o tile,
// per-thread 4b x 5o, double-buffered K chunks of 16.
template <int PH>
__global__ void __launch_bounds__(256)
gemm_kernel(float* __restrict__ Cout) {
    __shared__ float As[2][32][16];
    __shared__ float Bs[2][16][DD];

    const float* A    = (PH == 0) ? g_Qin : g_Acc;
    const float* Bt   = (PH == 0) ? g_Mt  : g_Pt;
    const float* bias = (PH == 0) ? g_m0  : g_p0;
    float* C          = (PH == 0) ? g_U   : Cout;

    int t = threadIdx.x;
    int ox = t & 31;
    int by = t >> 5;              // warp id 0..7
    int b0 = blockIdx.x * 32;

    float acc[4][5];
#pragma unroll
    for (int i = 0; i < 4; ++i)
#pragma unroll
        for (int j = 0; j < 5; ++j) acc[i][j] = 0.f;

    float bi[5];
#pragma unroll
    for (int j = 0; j < 5; ++j) bi[j] = bias[ox + 32 * j];

    // load indices
    int ar = t >> 3, ac = (t & 7) * 2;          // As: 32 rows x 8 float2
    int b0r = t / 40,       b0c = (t % 40) * 4; // Bs chunk 0
    int b1r = (t+256) / 40, b1c = ((t+256) % 40) * 4;
    int b2r = (t+512) / 40, b2c = ((t+512) % 40) * 4;

    float2 pa;
    float4 pb0, pb1, pb2;

    // prologue: load chunk 0
    pa  = *(const float2*)&A[(b0 + ar) * DD + ac];
    pb0 = *(const float4*)&Bt[b0r * DD + b0c];
    pb1 = *(const float4*)&Bt[b1r * DD + b1c];
    if (t < 128) pb2 = *(const float4*)&Bt[b2r * DD + b2c];
    As[0][ar][ac] = pa.x; As[0][ar][ac + 1] = pa.y;
    *(float4*)&Bs[0][b0r][b0c] = pb0;
    *(float4*)&Bs[0][b1r][b1c] = pb1;
    if (t < 128) *(float4*)&Bs[0][b2r][b2c] = pb2;

    for (int c = 0; c < DD / 16; ++c) {
        __syncthreads();
        int cur = c & 1;
        if (c + 1 < DD / 16) {
            int g0 = (c + 1) * 16;
            pa  = *(const float2*)&A[(b0 + ar) * DD + g0 + ac];
            pb0 = *(const float4*)&Bt[(g0 + b0r) * DD + b0c];
            pb1 = *(const float4*)&Bt[(g0 + b1r) * DD + b1c];
            if (t < 128) pb2 = *(const float4*)&Bt[(g0 + b2r) * DD + b2c];
        }
#pragma unroll
        for (int g = 0; g < 16; ++g) {
            float av[4], bv[5];
#pragma unroll
            for (int i = 0; i < 4; ++i) av[i] = As[cur][by + 8 * i][g];
#pragma unroll
            for (int j = 0; j < 5; ++j) bv[j] = Bs[cur][g][ox + 32 * j];
#pragma unroll
            for (int i = 0; i < 4; ++i)
#pragma unroll
                for (int j = 0; j < 5; ++j)
                    acc[i][j] = fmaf(av[i], bv[j], acc[i][j]);
        }
        if (c + 1 < DD / 16) {
            int nb = 1 - cur;
            As[nb][ar][ac] = pa.x; As[nb][ar][ac + 1] = pa.y;
            *(float4*)&Bs[nb][b0r][b0c] = pb0;
            *(float4*)&Bs[nb][b1r][b1c] = pb1;
            if (t < 128) *(float4*)&Bs[nb][b2r][b2c] = pb2;
        }
    }

#pragma unroll
    for (int i = 0; i < 4; ++i) {
        int b = b0 + by + 8 * i;
#pragma unroll
        for (int j = 0; j < 5; ++j)
            C[b * DD + ox + 32 * j] = acc[i][j] + bi[j];
    }
}

// ---------------- kernel 2: scores, softmax, gumbel/mask, accumulation ----------
// 1 block per target b, 512 threads (16 warps), each warp owns 4 neighbors.
__global__ void __launch_bounds__(512)
phase2_kernel(const float* __restrict__ x,
              const int* __restrict__ nbr_ids,
              const int* __restrict__ etime,
              const float* __restrict__ gum,
              float* __restrict__ out_mask) {
    __shared__ float ssc[KK];
    __shared__ float saw[KK];
    __shared__ float sg[KK];
    __shared__ float4 part[16][41];   // 16 warps x 40 float4 (padded to 41)

    int b = blockIdx.x;
    int t = threadIdx.x;
    int w = t >> 5;
    int lane = t & 31;
    int kb = w * 4;

    const float4* xv = (const float4*)x;
    const float4* tv = (const float4*)g_tbl;
    const float4* uv = (const float4*)g_U;

    int nid[4], et[4];
#pragma unroll
    for (int i = 0; i < 4; ++i) {
        nid[i] = nbr_ids[b * KK + kb + i];
        et[i]  = etime[b * KK + kb + i];
    }
    float4 xr[4], tr[4];
#pragma unroll
    for (int i = 0; i < 4; ++i) xr[i] = xv[nid[i] * 32 + lane];   // coalesced 512B row
#pragma unroll
    for (int i = 0; i < 4; ++i)
        tr[i] = (lane < 8) ? tv[et[i] * 8 + lane] : make_float4(0.f, 0.f, 0.f, 0.f);

    // gumbel noise precomputed by all warps (off warp0's critical path),
    // overlaps with the row gathers above
    if (lane < 4) {
        float u = gum[b * KK + kb + lane];
        sg[kb + lane] = -logf(-logf(u + 1e-10f) + 1e-10f);
    }

    float4 u4 = uv[b * 40 + lane];
    float4 ut4 = make_float4(0.f, 0.f, 0.f, 0.f);
    if (lane < 8) ut4 = uv[b * 40 + 32 + lane];
    float s0 = g_S0[b];

    float p[4];
#pragma unroll
    for (int i = 0; i < 4; ++i) {
        p[i] = u4.x * xr[i].x + u4.y * xr[i].y + u4.z * xr[i].z + u4.w * xr[i].w
             + ut4.x * tr[i].x + ut4.y * tr[i].y + ut4.z * tr[i].z + ut4.w * tr[i].w;
    }
    // batched 4-way reduction: 12 shuffles instead of 20
    p[0] += __shfl_xor_sync(0xffffffffu, p[0], 1);
    p[1] += __shfl_xor_sync(0xffffffffu, p[1], 1);
    p[2] += __shfl_xor_sync(0xffffffffu, p[2], 1);
    p[3] += __shfl_xor_sync(0xffffffffu, p[3], 1);
    float ra = (lane & 1) ? p[1] : p[0];
    float rb = (lane & 1) ? p[3] : p[2];
#pragma unroll
    for (int o = 2; o <= 16; o <<= 1) {
        ra += __shfl_xor_sync(0xffffffffu, ra, o);
        rb += __shfl_xor_sync(0xffffffffu, rb, o);
    }
    // even lanes hold sum(p0)/sum(p2), odd lanes sum(p1)/sum(p3)
    if (lane < 2) {
        ssc[kb + lane]     = ra + s0;
        ssc[kb + 2 + lane] = rb + s0;
    }
    __syncthreads();

    if (w == 0) {
        // softmax over 64 scores: lane handles l and l+32
        float a0 = ssc[lane], a1 = ssc[lane + 32];
        float m = fmaxf(a0, a1);
#pragma unroll
        for (int o = 16; o; o >>= 1) m = fmaxf(m, __shfl_xor_sync(0xffffffffu, m, o));
        float e0 = expf(a0 - m), e1 = expf(a1 - m);
        float s = e0 + e1;
#pragma unroll
        for (int o = 16; o; o >>= 1) s += __shfl_xor_sync(0xffffffffu, s, o);
        float aw0 = e0 / s, aw1 = e1 / s;
        saw[lane] = aw0;
        saw[lane + 32] = aw1;
        // gumbel softmax + threshold mask (TAU = 1), gumbel already in sg[]
        float z0 = aw0 + sg[lane], z1 = aw1 + sg[lane + 32];
        float zm = fmaxf(z0, z1);
#pragma unroll
        for (int o = 16; o; o >>= 1) zm = fmaxf(zm, __shfl_xor_sync(0xffffffffu, zm, o));
        float ez0 = expf(z0 - zm), ez1 = expf(z1 - zm);
        float zs = ez0 + ez1;
#pragma unroll
        for (int o = 16; o; o >>= 1) zs += __shfl_xor_sync(0xffffffffu, zs, o);
        out_mask[b * KK + lane]      = (ez0 / zs > 0.2f) ? 1.0f : 0.0f;
        out_mask[b * KK + lane + 32] = (ez1 / zs > 0.2f) ? 1.0f : 0.0f;
    }
    __syncthreads();

    // accumulate attn_w-weighted kv rows (kv still live in registers)
    float4 ax = make_float4(0.f, 0.f, 0.f, 0.f);
    float4 at = make_float4(0.f, 0.f, 0.f, 0.f);
#pragma unroll
    for (int i = 0; i < 4; ++i) {
        float aw = saw[kb + i];
        ax.x = fmaf(aw, xr[i].x, ax.x);
        ax.y = fmaf(aw, xr[i].y, ax.y);
        ax.z = fmaf(aw, xr[i].z, ax.z);
        ax.w = fmaf(aw, xr[i].w, ax.w);
        at.x = fmaf(aw, tr[i].x, at.x);
        at.y = fmaf(aw, tr[i].y, at.y);
        at.z = fmaf(aw, tr[i].z, at.z);
        at.w = fmaf(aw, tr[i].w, at.w);
    }
    part[w][lane] = ax;
    if (lane < 8) part[w][32 + lane] = at;
    __syncthreads();

    if (t < DD) {
        const float* pf = (const float*)part;   // row stride 41*4 = 164 floats
        float a = 0.f;
#pragma unroll
        for (int ww = 0; ww < 16; ++ww) a += pf[ww * 164 + t];
        g_Acc[b * DD + t] = a;
    }
}

// ---------------- kernel 3b: mlp dot + leaky relu epilogue ----------------------
// grid 128 x 1024; warp per target
__global__ void __launch_bounds__(1024)
epi_kernel(const float* __restrict__ attn,
           const float* __restrict__ ew,
           const float* __restrict__ mlpw,
           const float* __restrict__ mlpb,
           float* __restrict__ out2) {
    __shared__ float mw[DD + 2];   // [0..160]=mlp_w, [161]=mlp_b
    int t = threadIdx.x, w = t >> 5, lane = t & 31;
    if (t < DD + 1) mw[t] = mlpw[t];
    if (t == DD + 1) mw[DD + 1] = mlpb[0];
    __syncthreads();

    int b = blockIdx.x * 32 + w;
    float s = 0.f;
#pragma unroll
    for (int m = 0; m < 5; ++m) {
        int c = lane + 32 * m;
        s = fmaf(attn[b * DD + c], mw[c], s);
    }
#pragma unroll
    for (int o = 16; o; o >>= 1) s += __shfl_xor_sync(0xffffffffu, s, o);
#pragma unroll
    for (int r = 0; r < 2; ++r) {
        int k = lane + 32 * r;
        float e = ew[b * KK + k];
        float v = s + fmaf(e, mw[DD], mw[DD + 1]);
        out2[b * KK + k] = (v >= 0.f) ? v : 0.01f * v;
    }
}

// ---------------- launch --------------------------------------------------------
extern "C" void kernel_launch(void* const* d_in, const int* in_sizes, int n_in,
                              void* d_out, int out_size) {
    const float* x    = (const float*)d_in[0];
    const int*   tgt  = (const int*)  d_in[1];
    const int*   tt   = (const int*)  d_in[2];
    const int*   nbr  = (const int*)  d_in[3];
    const int*   et   = (const int*)  d_in[4];
    const float* ew   = (const float*)d_in[5];
    const float* gu   = (const float*)d_in[6];
    const float* tew  = (const float*)d_in[7];
    const float* teb  = (const float*)d_in[8];
    const float* ipw  = (const float*)d_in[9];
    const float* ipb  = (const float*)d_in[10];
    const float* outw = (const float*)d_in[11];
    const float* outb = (const float*)d_in[12];
    const float* mlpw = (const float*)d_in[13];
    const float* mlpb = (const float*)d_in[14];

    float* o1 = (float*)d_out;           // attn_output     [B, D]
    float* o2 = o1 + BB * DD;            // new_edge_weight [B, K]
    float* o3 = o2 + BB * KK;            // candidate_mask  [B, K]

    prep_kernel<<<2 * DD + 1, DD>>>(ipw, ipb, outw, outb);
    tbl_kernel<<<(NT * TE + 255) / 256, 256>>>(tew, teb);
    gather_kernel<<<128, 1024>>>(x, tgt, tt);
    gemm_kernel<0><<<128, 256>>>(nullptr);           // Qin @ M^T + m0 -> g_U
    phase2_kernel<<<BB, 512>>>(x, nbr, et, gu, o3);
    gemm_kernel<1><<<128, 256>>>(o1);                // Acc @ P^T + p0 -> attn_out
    epi_kernel<<<128, 1024>>>(o1, ew, mlpw, mlpb, o2);
}

// round 11
// speedup vs baseline: 2.2453x; 1.1373x over previous
#include <cuda_runtime.h>
#include <math.h>

// Problem constants
#define BB 4096
#define KK 64
#define FF 128
#define TE 32
#define DD 160
#define NT 10000
#define INV_SQRT_D 0.07905694150420949f   // 1/sqrt(160)
#define FULL 0xffffffffu

// ---------------- scratch (__device__ globals) ----------------------------------
__device__ __align__(16) float g_tbl[NT * TE];   // cos(t*w+b) table
__device__ __align__(16) float g_Mt[DD * DD];    // Mt[g][o] = (Wk^T Wq / sqrt(D))[o][g]
__device__ __align__(16) float g_Pt[DD * DD];    // Pt[g][e] = (out_w @ Wv)[e][g]
__device__ float g_m0[DD];
__device__ float g_w0[DD];
__device__ float g_p0[DD];
__device__ float g_b00[1];
__device__ __align__(16) float g_U[BB * DD];     // transformed queries
__device__ float g_S0[BB];                       // score bias
__device__ __align__(16) float g_Acc[BB * DD];   // attn-weighted kv accumulation

// ---------------- kernel 0a: fold weight matrices -------------------------------
__global__ void prep_kernel(const float* __restrict__ ipw,
                            const float* __restrict__ ipb,
                            const float* __restrict__ outw,
                            const float* __restrict__ outb) {
    int t = threadIdx.x;
    int bidx = blockIdx.x;
    if (bidx < DD) {
        int f = bidx;
        float acc = 0.f;
        for (int d = 0; d < DD; ++d)
            acc = fmaf(ipw[(DD + d) * DD + f], ipw[d * DD + t], acc);
        g_Mt[t * DD + f] = acc * INV_SQRT_D;           // transposed
    } else if (bidx < 2 * DD) {
        int e = bidx - DD;
        float acc = 0.f;
        for (int d = 0; d < DD; ++d)
            acc = fmaf(outw[e * DD + d], ipw[(2 * DD + d) * DD + t], acc);
        g_Pt[t * DD + e] = acc;                        // transposed
    } else {
        float m0 = 0.f, w0 = 0.f, p0 = 0.f;
        for (int d = 0; d < DD; ++d) {
            m0 = fmaf(ipw[(DD + d) * DD + t], ipb[d], m0);
            w0 = fmaf(ipw[d * DD + t], ipb[DD + d], w0);
            p0 = fmaf(outw[t * DD + d], ipb[2 * DD + d], p0);
        }
        g_m0[t] = m0 * INV_SQRT_D;
        g_w0[t] = w0 * INV_SQRT_D;
        g_p0[t] = p0 + outb[t];
        if (t == 0) {
            float b00 = 0.f;
            for (int d = 0; d < DD; ++d) b00 = fmaf(ipb[d], ipb[DD + d], b00);
            g_b00[0] = b00 * INV_SQRT_D;
        }
    }
}

// ---------------- kernel 0b: cos table -------------------------------------------
__global__ void tbl_kernel(const float* __restrict__ tw, const float* __restrict__ tb) {
    int idx = blockIdx.x * blockDim.x + threadIdx.x;
    if (idx >= NT * TE) return;
    int t = idx >> 5;
    int j = idx & 31;
    float arg = __fadd_rn(__fmul_rn((float)t, tw[j]), tb[j]);
    float kf = rintf(arg * 0.15915494309189535f);
    double r = fma(-(double)kf, 6.283185307179586, (double)arg);
    g_tbl[idx] = cosf((float)r);
}

// ---------------- fused GEMM: 16b x 160o tile, 256 blocks x 256 thr --------------
// PH0: A = gather(x, tbl) by target ids; C = g_U; side-product S0.
// PH1: A = g_Acc; C = out1 (attn_out); fused mlp-dot + leaky edge weights.
template <int PH>
__global__ void __launch_bounds__(256)
gemm_kernel(const float* __restrict__ x,
            const int* __restrict__ tgt_ids,
            const int* __restrict__ tgt_times,
            const float* __restrict__ ew,
            const float* __restrict__ mlpw,
            const float* __restrict__ mlpb,
            float* __restrict__ out1,
            float* __restrict__ out2) {
    __shared__ float As[2][16][16];
    __shared__ float Bs[2][16][DD];
    __shared__ float sw0[DD];
    __shared__ int   stg[16], stt[16];
    __shared__ float smlp[DD + 2];

    const float* Bt   = (PH == 0) ? g_Mt : g_Pt;
    const float* bias = (PH == 0) ? g_m0 : g_p0;

    int t = threadIdx.x;
    int ox = t & 31, by = t >> 5;        // warp 0..7
    int b0 = blockIdx.x * 16;

    if (PH == 0) {
        if (t < DD) sw0[t] = g_w0[t];
        if (t < 16) { stg[t] = tgt_ids[b0 + t]; stt[t] = tgt_times[b0 + t]; }
    } else {
        if (t < DD + 1) smlp[t] = mlpw[t];
        if (t == 0) smlp[DD + 1] = mlpb[0];
    }
    __syncthreads();

    int ar = t >> 4, ac = t & 15;
    int tg = 0, ttm = 0;
    if (PH == 0) { tg = stg[ar]; ttm = stt[ar]; }

    int i1 = t + 256, i2 = t + 512;
    int b0r = t / 40,  b0c = (t % 40) * 4;
    int b1r = i1 / 40, b1c = (i1 % 40) * 4;
    int b2r = i2 / 40, b2c = (i2 % 40) * 4;

    float acc[2][5];
#pragma unroll
    for (int i = 0; i < 2; ++i)
#pragma unroll
        for (int j = 0; j < 5; ++j) acc[i][j] = 0.f;
    float s0p = 0.f;

    float va;
    float4 pb0, pb1, pb2;

    // prologue chunk 0
    if (PH == 0)
        va = (ac < FF) ? x[tg * FF + ac] : g_tbl[ttm * TE + (ac - FF)];
    else
        va = g_Acc[(b0 + ar) * DD + ac];
    if (PH == 0) s0p = va * sw0[ac];
    pb0 = *(const float4*)&Bt[b0r * DD + b0c];
    pb1 = *(const float4*)&Bt[b1r * DD + b1c];
    if (t < 128) pb2 = *(const float4*)&Bt[b2r * DD + b2c];
    As[0][ar][ac] = va;
    *(float4*)&Bs[0][b0r][b0c] = pb0;
    *(float4*)&Bs[0][b1r][b1c] = pb1;
    if (t < 128) *(float4*)&Bs[0][b2r][b2c] = pb2;

    for (int c = 0; c < 10; ++c) {
        __syncthreads();
        int cur = c & 1;
        if (c < 9) {
            int g0 = (c + 1) * 16;
            int g = g0 + ac;
            if (PH == 0)
                va = (g < FF) ? x[tg * FF + g] : g_tbl[ttm * TE + (g - FF)];
            else
                va = g_Acc[(b0 + ar) * DD + g];
            if (PH == 0) s0p = fmaf(va, sw0[g], s0p);
            pb0 = *(const float4*)&Bt[(g0 + b0r) * DD + b0c];
            pb1 = *(const float4*)&Bt[(g0 + b1r) * DD + b1c];
            if (t < 128) pb2 = *(const float4*)&Bt[(g0 + b2r) * DD + b2c];
        }
#pragma unroll
        for (int g = 0; g < 16; ++g) {
            float av0 = As[cur][by][g];
            float av1 = As[cur][by + 8][g];
            float bv[5];
#pragma unroll
            for (int j = 0; j < 5; ++j) bv[j] = Bs[cur][g][ox + 32 * j];
#pragma unroll
            for (int j = 0; j < 5; ++j) {
                acc[0][j] = fmaf(av0, bv[j], acc[0][j]);
                acc[1][j] = fmaf(av1, bv[j], acc[1][j]);
            }
        }
        if (c < 9) {
            int nb = 1 - cur;
            As[nb][ar][ac] = va;
            *(float4*)&Bs[nb][b0r][b0c] = pb0;
            *(float4*)&Bs[nb][b1r][b1c] = pb1;
            if (t < 128) *(float4*)&Bs[nb][b2r][b2c] = pb2;
        }
    }

    float bi[5];
#pragma unroll
    for (int j = 0; j < 5; ++j) bi[j] = bias[ox + 32 * j];

    if (PH == 0) {
#pragma unroll
        for (int i = 0; i < 2; ++i)
#pragma unroll
            for (int j = 0; j < 5; ++j)
                g_U[(b0 + by + 8 * i) * DD + ox + 32 * j] = acc[i][j] + bi[j];
        // S0: reduce over the 16 threads of each row (16-lane segments)
#pragma unroll
        for (int off = 8; off; off >>= 1)
            s0p += __shfl_down_sync(FULL, s0p, off, 16);
        if (ac == 0) g_S0[b0 + ar] = s0p + g_b00[0];
    } else {
        float cb[2][5];
        float md0 = 0.f, md1 = 0.f;
#pragma unroll
        for (int j = 0; j < 5; ++j) {
            cb[0][j] = acc[0][j] + bi[j];
            cb[1][j] = acc[1][j] + bi[j];
            float mw = smlp[ox + 32 * j];
            md0 = fmaf(cb[0][j], mw, md0);
            md1 = fmaf(cb[1][j], mw, md1);
        }
#pragma unroll
        for (int i = 0; i < 2; ++i)
#pragma unroll
            for (int j = 0; j < 5; ++j)
                out1[(b0 + by + 8 * i) * DD + ox + 32 * j] = cb[i][j];
        // warp holds complete rows by and by+8 -> reduce mlp dot in-warp
        md0 += __shfl_xor_sync(FULL, md0, 1);
        md1 += __shfl_xor_sync(FULL, md1, 1);
        float ra = (ox & 1) ? md1 : md0;
#pragma unroll
        for (int o = 2; o <= 16; o <<= 1) ra += __shfl_xor_sync(FULL, ra, o);
        float m0 = __shfl_sync(FULL, ra, 0);   // row by
        float m1 = __shfl_sync(FULL, ra, 1);   // row by+8
        float wE = smlp[DD], bE = smlp[DD + 1];
#pragma unroll
        for (int rr = 0; rr < 2; ++rr) {
            int row = b0 + by + 8 * rr;
            float mm = rr ? m1 : m0;
#pragma unroll
            for (int q = 0; q < 2; ++q) {
                int k = ox + 32 * q;
                float v = mm + fmaf(ew[row * KK + k], wE, bE);
                out2[row * KK + k] = (v >= 0.f) ? v : 0.01f * v;
            }
        }
    }
}

// ---------------- phase2: warp-per-target online softmax -------------------------
// 512 blocks x 256 thr; each warp fully owns one target: single pass over 64
// neighbors (16 batches of 4), online max-rescaled softmax, no block syncs.
__global__ void __launch_bounds__(256)
phase2_kernel(const float* __restrict__ x,
              const int* __restrict__ nbr_ids,
              const int* __restrict__ etime,
              const float* __restrict__ gum,
              float* __restrict__ out_mask) {
    int t = threadIdx.x, w = t >> 5, lane = t & 31;
    int b = blockIdx.x * 8 + w;

    const float4* xv = (const float4*)x;
    const float4* tv = (const float4*)g_tbl;
    const float4* uv = (const float4*)g_U;

    int ids0 = nbr_ids[b * KK + lane];
    int ids1 = nbr_ids[b * KK + 32 + lane];
    int ets0 = etime[b * KK + lane];
    int ets1 = etime[b * KK + 32 + lane];
    float gu0 = gum[b * KK + lane];
    float gu1 = gum[b * KK + 32 + lane];

    float4 u4 = uv[b * 40 + lane];
    float4 ut4 = make_float4(0.f, 0.f, 0.f, 0.f);
    if (lane < 8) ut4 = uv[b * 40 + 32 + lane];
    float s0 = g_S0[b];

    float rm = -INFINITY, rs = 0.f;
    float4 ax = make_float4(0.f, 0.f, 0.f, 0.f);
    float4 at = make_float4(0.f, 0.f, 0.f, 0.f);
    float sc0 = 0.f, sc1 = 0.f;

#pragma unroll 4
    for (int j = 0; j < 16; ++j) {
        int kk = (4 * j) & 31;
        int idreg = (j < 8) ? ids0 : ids1;
        int etreg = (j < 8) ? ets0 : ets1;
        int nid[4], etv[4];
        float4 xr[4], tr[4];
#pragma unroll
        for (int i = 0; i < 4; ++i) {
            nid[i] = __shfl_sync(FULL, idreg, kk + i);
            etv[i] = __shfl_sync(FULL, etreg, kk + i);
        }
#pragma unroll
        for (int i = 0; i < 4; ++i) xr[i] = xv[nid[i] * 32 + lane];
#pragma unroll
        for (int i = 0; i < 4; ++i)
            tr[i] = (lane < 8) ? tv[etv[i] * 8 + lane] : make_float4(0.f, 0.f, 0.f, 0.f);

        float p[4];
#pragma unroll
        for (int i = 0; i < 4; ++i)
            p[i] = u4.x * xr[i].x + u4.y * xr[i].y + u4.z * xr[i].z + u4.w * xr[i].w
                 + ut4.x * tr[i].x + ut4.y * tr[i].y + ut4.z * tr[i].z + ut4.w * tr[i].w;

        p[0] += __shfl_xor_sync(FULL, p[0], 1);
        p[1] += __shfl_xor_sync(FULL, p[1], 1);
        p[2] += __shfl_xor_sync(FULL, p[2], 1);
        p[3] += __shfl_xor_sync(FULL, p[3], 1);
        float ra = (lane & 1) ? p[1] : p[0];
        float rb = (lane & 1) ? p[3] : p[2];
#pragma unroll
        for (int o = 2; o <= 16; o <<= 1) {
            ra += __shfl_xor_sync(FULL, ra, o);
            rb += __shfl_xor_sync(FULL, rb, o);
        }
        float sA = __shfl_sync(FULL, ra, 0) + s0;
        float sB = __shfl_sync(FULL, ra, 1) + s0;
        float sC = __shfl_sync(FULL, rb, 0) + s0;
        float sD = __shfl_sync(FULL, rb, 1) + s0;

        int rel = lane - kk;
        if (rel >= 0 && rel < 4) {
            float sv = (rel == 0) ? sA : (rel == 1) ? sB : (rel == 2) ? sC : sD;
            if (j < 8) sc0 = sv; else sc1 = sv;
        }

        // online softmax update
        float bm = fmaxf(fmaxf(sA, sB), fmaxf(sC, sD));
        float nm = fmaxf(rm, bm);
        float scale = expf(rm - nm);             // 0 on first batch (rm=-inf)
        float e0 = expf(sA - nm), e1 = expf(sB - nm);
        float e2 = expf(sC - nm), e3 = expf(sD - nm);
        rs = rs * scale + (e0 + e1) + (e2 + e3);
        ax.x = ax.x * scale; ax.y = ax.y * scale; ax.z = ax.z * scale; ax.w = ax.w * scale;
        at.x = at.x * scale; at.y = at.y * scale; at.z = at.z * scale; at.w = at.w * scale;
#pragma unroll
        for (int i = 0; i < 4; ++i) {
            float e = (i == 0) ? e0 : (i == 1) ? e1 : (i == 2) ? e2 : e3;
            ax.x = fmaf(e, xr[i].x, ax.x);
            ax.y = fmaf(e, xr[i].y, ax.y);
            ax.z = fmaf(e, xr[i].z, ax.z);
            ax.w = fmaf(e, xr[i].w, ax.w);
            at.x = fmaf(e, tr[i].x, at.x);
            at.y = fmaf(e, tr[i].y, at.y);
            at.z = fmaf(e, tr[i].z, at.z);
            at.w = fmaf(e, tr[i].w, at.w);
        }
        rm = nm;
    }

    float inv = 1.f / rs;
    float4 o4;
    o4.x = ax.x * inv; o4.y = ax.y * inv; o4.z = ax.z * inv; o4.w = ax.w * inv;
    ((float4*)&g_Acc[b * DD])[lane] = o4;
    if (lane < 8) {
        float4 o8;
        o8.x = at.x * inv; o8.y = at.y * inv; o8.z = at.z * inv; o8.w = at.w * inv;
        ((float4*)&g_Acc[b * DD])[32 + lane] = o8;
    }

    // gumbel mask: attn weights recomputed from stored raw scores
    float aw0 = expf(sc0 - rm) * inv;
    float aw1 = expf(sc1 - rm) * inv;
    float g0 = -logf(-logf(gu0 + 1e-10f) + 1e-10f);
    float g1 = -logf(-logf(gu1 + 1e-10f) + 1e-10f);
    float z0 = aw0 + g0, z1 = aw1 + g1;
    float zm = fmaxf(z0, z1);
#pragma unroll
    for (int o = 16; o; o >>= 1) zm = fmaxf(zm, __shfl_xor_sync(FULL, zm, o));
    float ez0 = expf(z0 - zm), ez1 = expf(z1 - zm);
    float zs = ez0 + ez1;
#pragma unroll
    for (int o = 16; o; o >>= 1) zs += __shfl_xor_sync(FULL, zs, o);
    out_mask[b * KK + lane]      = (ez0 / zs > 0.2f) ? 1.0f : 0.0f;
    out_mask[b * KK + 32 + lane] = (ez1 / zs > 0.2f) ? 1.0f : 0.0f;
}

// ---------------- launch ----------------------------------------------------------
extern "C" void kernel_launch(void* const* d_in, const int* in_sizes, int n_in,
                              void* d_out, int out_size) {
    const float* x    = (const float*)d_in[0];
    const int*   tgt  = (const int*)  d_in[1];
    const int*   tt   = (const int*)  d_in[2];
    const int*   nbr  = (const int*)  d_in[3];
    const int*   et   = (const int*)  d_in[4];
    const float* ew   = (const float*)d_in[5];
    const float* gu   = (const float*)d_in[6];
    const float* tew  = (const float*)d_in[7];
    const float* teb  = (const float*)d_in[8];
    const float* ipw  = (const float*)d_in[9];
    const float* ipb  = (const float*)d_in[10];
    const float* outw = (const float*)d_in[11];
    const float* outb = (const float*)d_in[12];
    const float* mlpw = (const float*)d_in[13];
    const float* mlpb = (const float*)d_in[14];

    float* o1 = (float*)d_out;           // attn_output     [B, D]
    float* o2 = o1 + BB * DD;            // new_edge_weight [B, K]
    float* o3 = o2 + BB * KK;            // candidate_mask  [B, K]

    prep_kernel<<<2 * DD + 1, DD>>>(ipw, ipb, outw, outb);
    tbl_kernel<<<(NT * TE + 255) / 256, 256>>>(tew, teb);
    // gemm<0>: fused gather + Qin@M^T + S0  -> g_U, g_S0
    gemm_kernel<0><<<256, 256>>>(x, tgt, tt, nullptr, nullptr, nullptr, nullptr, nullptr);
    phase2_kernel<<<BB / 8, 256>>>(x, nbr, et, gu, o3);
    // gemm<1>: Acc@P^T + p0 -> attn_out, fused mlp + leaky edge weights
    gemm_kernel<1><<<256, 256>>>(nullptr, nullptr, nullptr, ew, mlpw, mlpb, o1, o2);
}

// round 12
// speedup vs baseline: 2.4160x; 1.0760x over previous
#include <cuda_runtime.h>
#include <math.h>

// Problem constants
#define BB 4096
#define KK 64
#define FF 128
#define TE 32
#define DD 160
#define NT 10000
#define INV_SQRT_D 0.07905694150420949f   // 1/sqrt(160)
#define FULL 0xffffffffu

// ---------------- scratch (__device__ globals) ----------------------------------
__device__ __align__(16) float g_tbl[NT * TE];   // cos(t*w+b) table
__device__ __align__(16) float g_Mt[DD * DD];    // Mt[g][o] = (Wk^T Wq / sqrt(D))[o][g]
__device__ __align__(16) float g_Pt[DD * DD];    // Pt[g][e] = (out_w @ Wv)[e][g]
__device__ float g_m0[DD];
__device__ float g_w0[DD];
__device__ float g_p0[DD];
__device__ float g_b00[1];
__device__ __align__(16) float g_U[BB * DD];     // transformed queries
__device__ float g_S0[BB];                       // score bias
__device__ __align__(16) float g_Acc[BB * DD];   // attn-weighted kv accumulation

// ---------------- kernel 0: fold weights + cos table (merged) --------------------
// blocks [0, 2*DD]: weight folding (160 active threads); rest: cos table
#define PREP_BLKS (2 * DD + 1)
__global__ void __launch_bounds__(256)
setup_kernel(const float* __restrict__ ipw,
             const float* __restrict__ ipb,
             const float* __restrict__ outw,
             const float* __restrict__ outb,
             const float* __restrict__ tw,
             const float* __restrict__ tb) {
    int bidx = blockIdx.x;
    int t = threadIdx.x;
    if (bidx < PREP_BLKS) {
        if (t >= DD) return;
        if (bidx < DD) {
            int f = bidx;
            float acc = 0.f;
            for (int d = 0; d < DD; ++d)
                acc = fmaf(ipw[(DD + d) * DD + f], ipw[d * DD + t], acc);
            g_Mt[t * DD + f] = acc * INV_SQRT_D;           // transposed
        } else if (bidx < 2 * DD) {
            int e = bidx - DD;
            float acc = 0.f;
            for (int d = 0; d < DD; ++d)
                acc = fmaf(outw[e * DD + d], ipw[(2 * DD + d) * DD + t], acc);
            g_Pt[t * DD + e] = acc;                        // transposed
        } else {
            float m0 = 0.f, w0 = 0.f, p0 = 0.f;
            for (int d = 0; d < DD; ++d) {
                m0 = fmaf(ipw[(DD + d) * DD + t], ipb[d], m0);
                w0 = fmaf(ipw[d * DD + t], ipb[DD + d], w0);
                p0 = fmaf(outw[t * DD + d], ipb[2 * DD + d], p0);
            }
            g_m0[t] = m0 * INV_SQRT_D;
            g_w0[t] = w0 * INV_SQRT_D;
            g_p0[t] = p0 + outb[t];
            if (t == 0) {
                float b00 = 0.f;
                for (int d = 0; d < DD; ++d) b00 = fmaf(ipb[d], ipb[DD + d], b00);
                g_b00[0] = b00 * INV_SQRT_D;
            }
        }
    } else {
        int idx = (bidx - PREP_BLKS) * 256 + t;
        if (idx >= NT * TE) return;
        int tt = idx >> 5;
        int j = idx & 31;
        float arg = __fadd_rn(__fmul_rn((float)tt, tw[j]), tb[j]);
        float kf = rintf(arg * 0.15915494309189535f);
        double r = fma(-(double)kf, 6.283185307179586, (double)arg);
        g_tbl[idx] = cosf((float)r);
    }
}

// ---------------- fused GEMM: 16b x 160o tile, 256 blocks x 256 thr --------------
// PH0: A = gather(x, tbl) by target ids; C = g_U; side-product S0.
// PH1: A = g_Acc; C = out1 (attn_out); fused mlp-dot + leaky edge weights.
template <int PH>
__global__ void __launch_bounds__(256)
gemm_kernel(const float* __restrict__ x,
            const int* __restrict__ tgt_ids,
            const int* __restrict__ tgt_times,
            const float* __restrict__ ew,
            const float* __restrict__ mlpw,
            const float* __restrict__ mlpb,
            float* __restrict__ out1,
            float* __restrict__ out2) {
    __shared__ float As[2][16][16];
    __shared__ float Bs[2][16][DD];
    __shared__ float sw0[DD];
    __shared__ int   stg[16], stt[16];
    __shared__ float smlp[DD + 2];

    const float* Bt   = (PH == 0) ? g_Mt : g_Pt;
    const float* bias = (PH == 0) ? g_m0 : g_p0;

    int t = threadIdx.x;
    int ox = t & 31, by = t >> 5;        // warp 0..7
    int b0 = blockIdx.x * 16;

    if (PH == 0) {
        if (t < DD) sw0[t] = g_w0[t];
        if (t < 16) { stg[t] = tgt_ids[b0 + t]; stt[t] = tgt_times[b0 + t]; }
    } else {
        if (t < DD + 1) smlp[t] = mlpw[t];
        if (t == 0) smlp[DD + 1] = mlpb[0];
    }
    __syncthreads();

    int ar = t >> 4, ac = t & 15;
    int tg = 0, ttm = 0;
    if (PH == 0) { tg = stg[ar]; ttm = stt[ar]; }

    int i1 = t + 256, i2 = t + 512;
    int b0r = t / 40,  b0c = (t % 40) * 4;
    int b1r = i1 / 40, b1c = (i1 % 40) * 4;
    int b2r = i2 / 40, b2c = (i2 % 40) * 4;

    float acc[2][5];
#pragma unroll
    for (int i = 0; i < 2; ++i)
#pragma unroll
        for (int j = 0; j < 5; ++j) acc[i][j] = 0.f;
    float s0p = 0.f;

    float va;
    float4 pb0, pb1, pb2;

    // prologue chunk 0
    if (PH == 0)
        va = (ac < FF) ? x[tg * FF + ac] : g_tbl[ttm * TE + (ac - FF)];
    else
        va = g_Acc[(b0 + ar) * DD + ac];
    if (PH == 0) s0p = va * sw0[ac];
    pb0 = *(const float4*)&Bt[b0r * DD + b0c];
    pb1 = *(const float4*)&Bt[b1r * DD + b1c];
    if (t < 128) pb2 = *(const float4*)&Bt[b2r * DD + b2c];
    As[0][ar][ac] = va;
    *(float4*)&Bs[0][b0r][b0c] = pb0;
    *(float4*)&Bs[0][b1r][b1c] = pb1;
    if (t < 128) *(float4*)&Bs[0][b2r][b2c] = pb2;

    for (int c = 0; c < 10; ++c) {
        __syncthreads();
        int cur = c & 1;
        if (c < 9) {
            int g0 = (c + 1) * 16;
            int g = g0 + ac;
            if (PH == 0)
                va = (g < FF) ? x[tg * FF + g] : g_tbl[ttm * TE + (g - FF)];
            else
                va = g_Acc[(b0 + ar) * DD + g];
            if (PH == 0) s0p = fmaf(va, sw0[g], s0p);
            pb0 = *(const float4*)&Bt[(g0 + b0r) * DD + b0c];
            pb1 = *(const float4*)&Bt[(g0 + b1r) * DD + b1c];
            if (t < 128) pb2 = *(const float4*)&Bt[(g0 + b2r) * DD + b2c];
        }
#pragma unroll
        for (int g = 0; g < 16; ++g) {
            float av0 = As[cur][by][g];
            float av1 = As[cur][by + 8][g];
            float bv[5];
#pragma unroll
            for (int j = 0; j < 5; ++j) bv[j] = Bs[cur][g][ox + 32 * j];
#pragma unroll
            for (int j = 0; j < 5; ++j) {
                acc[0][j] = fmaf(av0, bv[j], acc[0][j]);
                acc[1][j] = fmaf(av1, bv[j], acc[1][j]);
            }
        }
        if (c < 9) {
            int nb = 1 - cur;
            As[nb][ar][ac] = va;
            *(float4*)&Bs[nb][b0r][b0c] = pb0;
            *(float4*)&Bs[nb][b1r][b1c] = pb1;
            if (t < 128) *(float4*)&Bs[nb][b2r][b2c] = pb2;
        }
    }

    float bi[5];
#pragma unroll
    for (int j = 0; j < 5; ++j) bi[j] = bias[ox + 32 * j];

    if (PH == 0) {
#pragma unroll
        for (int i = 0; i < 2; ++i)
#pragma unroll
            for (int j = 0; j < 5; ++j)
                g_U[(b0 + by + 8 * i) * DD + ox + 32 * j] = acc[i][j] + bi[j];
        // S0: reduce over the 16 threads of each row (16-lane segments)
#pragma unroll
        for (int off = 8; off; off >>= 1)
            s0p += __shfl_down_sync(FULL, s0p, off, 16);
        if (ac == 0) g_S0[b0 + ar] = s0p + g_b00[0];
    } else {
        float cb[2][5];
        float md0 = 0.f, md1 = 0.f;
#pragma unroll
        for (int j = 0; j < 5; ++j) {
            cb[0][j] = acc[0][j] + bi[j];
            cb[1][j] = acc[1][j] + bi[j];
            float mw = smlp[ox + 32 * j];
            md0 = fmaf(cb[0][j], mw, md0);
            md1 = fmaf(cb[1][j], mw, md1);
        }
#pragma unroll
        for (int i = 0; i < 2; ++i)
#pragma unroll
            for (int j = 0; j < 5; ++j)
                out1[(b0 + by + 8 * i) * DD + ox + 32 * j] = cb[i][j];
        // warp holds complete rows by and by+8 -> reduce mlp dot in-warp
        md0 += __shfl_xor_sync(FULL, md0, 1);
        md1 += __shfl_xor_sync(FULL, md1, 1);
        float ra = (ox & 1) ? md1 : md0;
#pragma unroll
        for (int o = 2; o <= 16; o <<= 1) ra += __shfl_xor_sync(FULL, ra, o);
        float m0 = __shfl_sync(FULL, ra, 0);   // row by
        float m1 = __shfl_sync(FULL, ra, 1);   // row by+8
        float wE = smlp[DD], bE = smlp[DD + 1];
#pragma unroll
        for (int rr = 0; rr < 2; ++rr) {
            int row = b0 + by + 8 * rr;
            float mm = rr ? m1 : m0;
#pragma unroll
            for (int q = 0; q < 2; ++q) {
                int k = ox + 32 * q;
                float v = mm + fmaf(ew[row * KK + k], wE, bE);
                out2[row * KK + k] = (v >= 0.f) ? v : 0.01f * v;
            }
        }
    }
}

// ---------------- phase2: warp-per-target, two-pass softmax ----------------------
// Pass A: all 64 scores, batches fully independent (no broadcasts needed — the
// owner lane of each neighbor ends the butterfly already holding its score).
// Pass B: re-gather rows (L2-hot) and accumulate with final weights.
__global__ void __launch_bounds__(256)
phase2_kernel(const float* __restrict__ x,
              const int* __restrict__ nbr_ids,
              const int* __restrict__ etime,
              const float* __restrict__ gum,
              float* __restrict__ out_mask) {
    int t = threadIdx.x, w = t >> 5, lane = t & 31;
    int b = blockIdx.x * 8 + w;

    const float4* xv = (const float4*)x;
    const float4* tv = (const float4*)g_tbl;
    const float4* uv = (const float4*)g_U;

    int ids0 = nbr_ids[b * KK + lane];
    int ids1 = nbr_ids[b * KK + 32 + lane];
    int ets0 = etime[b * KK + lane];
    int ets1 = etime[b * KK + 32 + lane];
    float gu0 = gum[b * KK + lane];
    float gu1 = gum[b * KK + 32 + lane];

    float4 u4 = uv[b * 40 + lane];
    float4 ut4 = make_float4(0.f, 0.f, 0.f, 0.f);
    if (lane < 8) ut4 = uv[b * 40 + 32 + lane];
    float s0 = g_S0[b];

    float sc0 = 0.f, sc1 = 0.f;

    // -------- pass A: scores (independent batches, zero broadcasts) --------
#pragma unroll
    for (int j = 0; j < 16; ++j) {
        int kk = (4 * j) & 31;
        int idreg = (j < 8) ? ids0 : ids1;
        int etreg = (j < 8) ? ets0 : ets1;
        int nid[4], etv[4];
#pragma unroll
        for (int i = 0; i < 4; ++i) {
            nid[i] = __shfl_sync(FULL, idreg, kk + i);
            etv[i] = __shfl_sync(FULL, etreg, kk + i);
        }
        float4 xr[4], tr[4];
#pragma unroll
        for (int i = 0; i < 4; ++i) xr[i] = xv[nid[i] * 32 + lane];
#pragma unroll
        for (int i = 0; i < 4; ++i)
            tr[i] = (lane < 8) ? tv[etv[i] * 8 + lane] : make_float4(0.f, 0.f, 0.f, 0.f);

        float p[4];
#pragma unroll
        for (int i = 0; i < 4; ++i)
            p[i] = u4.x * xr[i].x + u4.y * xr[i].y + u4.z * xr[i].z + u4.w * xr[i].w
                 + ut4.x * tr[i].x + ut4.y * tr[i].y + ut4.z * tr[i].z + ut4.w * tr[i].w;

        p[0] += __shfl_xor_sync(FULL, p[0], 1);
        p[1] += __shfl_xor_sync(FULL, p[1], 1);
        p[2] += __shfl_xor_sync(FULL, p[2], 1);
        p[3] += __shfl_xor_sync(FULL, p[3], 1);
        float ra = (lane & 1) ? p[1] : p[0];
        float rb = (lane & 1) ? p[3] : p[2];
#pragma unroll
        for (int o = 2; o <= 16; o <<= 1) {
            ra += __shfl_xor_sync(FULL, ra, o);
            rb += __shfl_xor_sync(FULL, rb, o);
        }
        // owner lanes kk..kk+3 already hold their own full sums:
        // kk+0 (even): ra=sumP0, kk+1 (odd): ra=sumP1, kk+2: rb=sumP2, kk+3: rb=sumP3
        int rel = lane - kk;
        if (rel >= 0 && rel < 4) {
            float sv = ((rel < 2) ? ra : rb) + s0;
            if (j < 8) sc0 = sv; else sc1 = sv;
        }
    }

    // -------- softmax over 64 scores (2 per lane) --------
    float m = fmaxf(sc0, sc1);
#pragma unroll
    for (int o = 16; o; o >>= 1) m = fmaxf(m, __shfl_xor_sync(FULL, m, o));
    float e0 = expf(sc0 - m), e1 = expf(sc1 - m);
    float s = e0 + e1;
#pragma unroll
    for (int o = 16; o; o >>= 1) s += __shfl_xor_sync(FULL, s, o);
    float inv = 1.f / s;
    float aw0 = e0 * inv, aw1 = e1 * inv;

    // -------- gumbel mask --------
    float g0 = -logf(-logf(gu0 + 1e-10f) + 1e-10f);
    float g1 = -logf(-logf(gu1 + 1e-10f) + 1e-10f);
    float z0 = aw0 + g0, z1 = aw1 + g1;
    float zm = fmaxf(z0, z1);
#pragma unroll
    for (int o = 16; o; o >>= 1) zm = fmaxf(zm, __shfl_xor_sync(FULL, zm, o));
    float ez0 = expf(z0 - zm), ez1 = expf(z1 - zm);
    float zs = ez0 + ez1;
#pragma unroll
    for (int o = 16; o; o >>= 1) zs += __shfl_xor_sync(FULL, zs, o);
    out_mask[b * KK + lane]      = (ez0 / zs > 0.2f) ? 1.0f : 0.0f;
    out_mask[b * KK + 32 + lane] = (ez1 / zs > 0.2f) ? 1.0f : 0.0f;

    // -------- pass B: weighted accumulation (rows L2-hot, independent) --------
    float4 ax = make_float4(0.f, 0.f, 0.f, 0.f);
    float4 at = make_float4(0.f, 0.f, 0.f, 0.f);
#pragma unroll
    for (int j = 0; j < 16; ++j) {
        int kk = (4 * j) & 31;
        int idreg = (j < 8) ? ids0 : ids1;
        int etreg = (j < 8) ? ets0 : ets1;
        float awreg = (j < 8) ? aw0 : aw1;
        int nid[4], etv[4];
        float wv[4];
#pragma unroll
        for (int i = 0; i < 4; ++i) {
            nid[i] = __shfl_sync(FULL, idreg, kk + i);
            etv[i] = __shfl_sync(FULL, etreg, kk + i);
            wv[i]  = __shfl_sync(FULL, awreg, kk + i);
        }
        float4 xr[4], tr[4];
#pragma unroll
        for (int i = 0; i < 4; ++i) xr[i] = xv[nid[i] * 32 + lane];
#pragma unroll
        for (int i = 0; i < 4; ++i)
            tr[i] = (lane < 8) ? tv[etv[i] * 8 + lane] : make_float4(0.f, 0.f, 0.f, 0.f);
#pragma unroll
        for (int i = 0; i < 4; ++i) {
            ax.x = fmaf(wv[i], xr[i].x, ax.x);
            ax.y = fmaf(wv[i], xr[i].y, ax.y);
            ax.z = fmaf(wv[i], xr[i].z, ax.z);
            ax.w = fmaf(wv[i], xr[i].w, ax.w);
            at.x = fmaf(wv[i], tr[i].x, at.x);
            at.y = fmaf(wv[i], tr[i].y, at.y);
            at.z = fmaf(wv[i], tr[i].z, at.z);
            at.w = fmaf(wv[i], tr[i].w, at.w);
        }
    }

    ((float4*)&g_Acc[b * DD])[lane] = ax;
    if (lane < 8)
        ((float4*)&g_Acc[b * DD])[32 + lane] = at;
}

// ---------------- launch ----------------------------------------------------------
extern "C" void kernel_launch(void* const* d_in, const int* in_sizes, int n_in,
                              void* d_out, int out_size) {
    const float* x    = (const float*)d_in[0];
    const int*   tgt  = (const int*)  d_in[1];
    const int*   tt   = (const int*)  d_in[2];
    const int*   nbr  = (const int*)  d_in[3];
    const int*   et   = (const int*)  d_in[4];
    const float* ew   = (const float*)d_in[5];
    const float* gu   = (const float*)d_in[6];
    const float* tew  = (const float*)d_in[7];
    const float* teb  = (const float*)d_in[8];
    const float* ipw  = (const float*)d_in[9];
    const float* ipb  = (const float*)d_in[10];
    const float* outw = (const float*)d_in[11];
    const float* outb = (const float*)d_in[12];
    const float* mlpw = (const float*)d_in[13];
    const float* mlpb = (const float*)d_in[14];

    float* o1 = (float*)d_out;           // attn_output     [B, D]
    float* o2 = o1 + BB * DD;            // new_edge_weight [B, K]
    float* o3 = o2 + BB * KK;            // candidate_mask  [B, K]

    int tbl_blks = (NT * TE + 255) / 256;
    setup_kernel<<<PREP_BLKS + tbl_blks, 256>>>(ipw, ipb, outw, outb, tew, teb);
    // gemm<0>: fused gather + Qin@M^T + S0  -> g_U, g_S0
    gemm_kernel<0><<<256, 256>>>(x, tgt, tt, nullptr, nullptr, nullptr, nullptr, nullptr);
    phase2_kernel<<<BB / 8, 256>>>(x, nbr, et, gu, o3);
    // gemm<1>: Acc@P^T + p0 -> attn_out, fused mlp + leaky edge weights
    gemm_kernel<1><<<256, 256>>>(nullptr, nullptr, nullptr, ew, mlpw, mlpb, o1, o2);
}